// round 8
// baseline (speedup 1.0000x reference)
#include <cuda_runtime.h>
#include <cuda_bf16.h>
#include <cstdint>

#define NN   50000
#define EE   800000
#define C    256
#define MPAD 50048          // 391 * 128

// ---------------------------------------------------------------------------
// Scratch (__device__ globals, allocation-free rule)
// ---------------------------------------------------------------------------
__device__ __align__(16) float g_t[(size_t)NN * C];            // GEMM out (pre-scaled)
__device__ __align__(16) __nv_bfloat16 g_ahi[(size_t)MPAD * C];
__device__ __align__(16) __nv_bfloat16 g_alo[(size_t)MPAD * C];
__device__ __align__(16) __nv_bfloat16 g_w1hi[C * C];   // B^T layout [N][K]
__device__ __align__(16) __nv_bfloat16 g_w1lo[C * C];
__device__ __align__(16) __nv_bfloat16 g_w2hi[C * C];
__device__ __align__(16) __nv_bfloat16 g_w2lo[C * C];
__device__ float g_dinv[NN];
__device__ int   g_deg[NN];
__device__ int   g_rowptr[NN + 1];
__device__ int   g_cursor[NN];
__device__ int   g_csrc[EE];

__device__ __forceinline__ uint32_t smem_u32(const void* p) {
    uint32_t a;
    asm("{ .reg .u64 t; cvta.to.shared.u64 t, %1; cvt.u32.u64 %0, t; }"
        : "=r"(a) : "l"(p));
    return a;
}

// ---------------------------------------------------------------------------
// Degree / CSR build
// ---------------------------------------------------------------------------
__global__ void deg_init(int* deg, int n) {
    int i = blockIdx.x * blockDim.x + threadIdx.x;
    if (i < n) deg[i] = 0;
}
__global__ void deg_accum(const int* __restrict__ dst, int* deg, int e) {
    int i = blockIdx.x * blockDim.x + threadIdx.x;
    if (i < e) atomicAdd(&deg[dst[i]], 1);
}
__global__ void scan_build(const int* __restrict__ deg, int* __restrict__ row_ptr,
                           int* __restrict__ cursor, float* __restrict__ dinv, int n) {
    __shared__ int part[1024];
    const int T = 1024;
    int tid = threadIdx.x;
    int chunk = (n + T - 1) / T;
    int beg = tid * chunk;
    int end = min(beg + chunk, n);
    int s = 0;
    for (int i = beg; i < end; i++) s += deg[i];
    part[tid] = s;
    __syncthreads();
    for (int off = 1; off < T; off <<= 1) {
        int v = part[tid];
        int u = (tid >= off) ? part[tid - off] : 0;
        __syncthreads();
        part[tid] = v + u;
        __syncthreads();
    }
    int run = (tid > 0) ? part[tid - 1] : 0;
    for (int i = beg; i < end; i++) {
        int c = deg[i];
        row_ptr[i] = run;
        cursor[i] = run;
        dinv[i] = rsqrtf((float)(c + 1));
        run += c;
    }
    if (tid == T - 1) row_ptr[n] = part[T - 1];
}
__global__ void csr_fill(const int* __restrict__ src, const int* __restrict__ dst,
                         int* cursor, int* __restrict__ csrc, int e) {
    int i = blockIdx.x * blockDim.x + threadIdx.x;
    if (i < e) {
        int p = atomicAdd(&cursor[dst[i]], 1);
        csrc[p] = src[i];
    }
}

// ---------------------------------------------------------------------------
// Conversion: fp32 -> (bf16 hi, bf16 lo)
// ---------------------------------------------------------------------------
union BF2 { __nv_bfloat162 h2; uint32_t u; };

__device__ __forceinline__ void split_bf16(float v, __nv_bfloat16& hi, __nv_bfloat16& lo) {
    hi = __float2bfloat16(v);
    lo = __float2bfloat16(v - __bfloat162float(hi));
}

__global__ void conv_x(const float* __restrict__ x, __nv_bfloat16* __restrict__ hi,
                       __nv_bfloat16* __restrict__ lo, int M) {
    int i = blockIdx.x * blockDim.x + threadIdx.x;      // float4 index
    if (i >= MPAD * (C / 4)) return;
    int r = i >> 6;
    float4 v = (r < M) ? __ldg((const float4*)x + i) : make_float4(0.f, 0.f, 0.f, 0.f);
    __nv_bfloat16 h0, h1, h2, h3, l0, l1, l2, l3;
    split_bf16(v.x, h0, l0); split_bf16(v.y, h1, l1);
    split_bf16(v.z, h2, l2); split_bf16(v.w, h3, l3);
    BF2 a, b; uint2 o;
    a.h2 = __nv_bfloat162(h0, h1); b.h2 = __nv_bfloat162(h2, h3);
    o.x = a.u; o.y = b.u;
    ((uint2*)hi)[i] = o;
    a.h2 = __nv_bfloat162(l0, l1); b.h2 = __nv_bfloat162(l2, l3);
    o.x = a.u; o.y = b.u;
    ((uint2*)lo)[i] = o;
}

// W [K,N] fp32 -> B^T [N][K] bf16 hi/lo
__global__ void conv_w(const float* __restrict__ W, __nv_bfloat16* __restrict__ hi,
                       __nv_bfloat16* __restrict__ lo) {
    int i = blockIdx.x * blockDim.x + threadIdx.x;      // over 256*64
    if (i >= C * (C / 4)) return;
    int n = i >> 6;
    int k4 = (i & 63) * 4;
    __nv_bfloat16 hs[4], ls[4];
    #pragma unroll
    for (int j = 0; j < 4; j++)
        split_bf16(__ldg(&W[(size_t)(k4 + j) * C + n]), hs[j], ls[j]);
    BF2 a, b; uint2 o;
    a.h2 = __nv_bfloat162(hs[0], hs[1]); b.h2 = __nv_bfloat162(hs[2], hs[3]);
    o.x = a.u; o.y = b.u;
    ((uint2*)hi)[i] = o;
    a.h2 = __nv_bfloat162(ls[0], ls[1]); b.h2 = __nv_bfloat162(ls[2], ls[3]);
    o.x = a.u; o.y = b.u;
    ((uint2*)lo)[i] = o;
}

// ---------------------------------------------------------------------------
// mma.sync bf16 GEMM (R5-proven): Hs = dinv[row] * (Ahi*Bhi + Alo*Bhi + Ahi*Blo)
// CTA 128x128, 8 warps of 32x64. K-chunks of 32. Bt is [N][K] ("col" operand).
// ---------------------------------------------------------------------------
#define LDS_PAD 40            // 32 + 8 pad (bf16 elems per smem row)

__device__ __forceinline__ void ldsm4(uint32_t* r, uint32_t addr) {
    asm volatile("ldmatrix.sync.aligned.m8n8.x4.shared.b16 {%0,%1,%2,%3}, [%4];"
                 : "=r"(r[0]), "=r"(r[1]), "=r"(r[2]), "=r"(r[3]) : "r"(addr));
}
__device__ __forceinline__ void mma16816(float* c, const uint32_t* a, const uint32_t* b) {
    asm volatile("mma.sync.aligned.m16n8k16.row.col.f32.bf16.bf16.f32 "
                 "{%0,%1,%2,%3}, {%4,%5,%6,%7}, {%8,%9}, {%0,%1,%2,%3};"
                 : "+f"(c[0]), "+f"(c[1]), "+f"(c[2]), "+f"(c[3])
                 : "r"(a[0]), "r"(a[1]), "r"(a[2]), "r"(a[3]), "r"(b[0]), "r"(b[1]));
}

__global__ __launch_bounds__(256)
void mma_gemm(const __nv_bfloat16* __restrict__ Ahi, const __nv_bfloat16* __restrict__ Alo,
              const __nv_bfloat16* __restrict__ Bhi, const __nv_bfloat16* __restrict__ Blo,
              float* __restrict__ Hs, const float* __restrict__ dinv, int M) {
    __shared__ __nv_bfloat16 sAh[128][LDS_PAD];
    __shared__ __nv_bfloat16 sAl[128][LDS_PAD];
    __shared__ __nv_bfloat16 sBh[128][LDS_PAD];
    __shared__ __nv_bfloat16 sBl[128][LDS_PAD];

    int tid = threadIdx.x, lane = tid & 31, wid = tid >> 5;
    int r0 = blockIdx.x * 128;
    int n0c = blockIdx.y * 128;          // CTA col base
    int wm = (wid & 3) * 32;             // warp row offset in tile
    int wn = (wid >> 2) * 64;            // warp col offset in tile

    // ldmatrix lane address components
    int aRow = lane & 15;
    int aCol = (lane >> 4) * 8;
    int bRow = (lane & 7) + ((lane >> 4) == 1 ? 8 : 0);
    int bCol = ((lane >> 3) & 1) * 8;

    uint32_t sbAh = smem_u32(sAh), sbAl = smem_u32(sAl);
    uint32_t sbBh = smem_u32(sBh), sbBl = smem_u32(sBl);

    // global staging map: 512 uint4 per tile, 2 per thread
    int gi0 = tid, gi1 = tid + 256;
    int gr0 = gi0 >> 2, gc0 = (gi0 & 3) * 8;
    int gr1 = gi1 >> 2, gc1 = (gi1 & 3) * 8;

    float acc[2][8][4] = {};

    #pragma unroll 1
    for (int kc = 0; kc < 8; kc++) {
        int k0 = kc * 32;
        // stage A (rows r0+gr, cols k0+gc) and B^T (rows n0c+gr, cols k0+gc)
        {
            const char* pAh = (const char*)(Ahi + (size_t)(r0 + gr0) * C + k0 + gc0);
            const char* pAl = (const char*)(Alo + (size_t)(r0 + gr0) * C + k0 + gc0);
            const char* pBh = (const char*)(Bhi + (size_t)(n0c + gr0) * C + k0 + gc0);
            const char* pBl = (const char*)(Blo + (size_t)(n0c + gr0) * C + k0 + gc0);
            *(uint4*)&sAh[gr0][gc0] = *(const uint4*)pAh;
            *(uint4*)&sAl[gr0][gc0] = *(const uint4*)pAl;
            *(uint4*)&sBh[gr0][gc0] = *(const uint4*)pBh;
            *(uint4*)&sBl[gr0][gc0] = *(const uint4*)pBl;
            const char* qAh = (const char*)(Ahi + (size_t)(r0 + gr1) * C + k0 + gc1);
            const char* qAl = (const char*)(Alo + (size_t)(r0 + gr1) * C + k0 + gc1);
            const char* qBh = (const char*)(Bhi + (size_t)(n0c + gr1) * C + k0 + gc1);
            const char* qBl = (const char*)(Blo + (size_t)(n0c + gr1) * C + k0 + gc1);
            *(uint4*)&sAh[gr1][gc1] = *(const uint4*)qAh;
            *(uint4*)&sAl[gr1][gc1] = *(const uint4*)qAl;
            *(uint4*)&sBh[gr1][gc1] = *(const uint4*)qBh;
            *(uint4*)&sBl[gr1][gc1] = *(const uint4*)qBl;
        }
        __syncthreads();

        #pragma unroll
        for (int ks = 0; ks < 32; ks += 16) {
            uint32_t ah[2][4], al[2][4];
            #pragma unroll
            for (int mt = 0; mt < 2; mt++) {
                uint32_t off = (uint32_t)((wm + mt * 16 + aRow) * LDS_PAD + ks + aCol) * 2;
                ldsm4(ah[mt], sbAh + off);
                ldsm4(al[mt], sbAl + off);
            }
            #pragma unroll
            for (int nq = 0; nq < 4; nq++) {
                uint32_t bh[4], bl[4];
                uint32_t off = (uint32_t)((wn + nq * 16 + bRow) * LDS_PAD + ks + bCol) * 2;
                ldsm4(bh, sbBh + off);
                ldsm4(bl, sbBl + off);
                #pragma unroll
                for (int sub = 0; sub < 2; sub++) {
                    int nt = nq * 2 + sub;
                    #pragma unroll
                    for (int mt = 0; mt < 2; mt++) {
                        mma16816(acc[mt][nt], ah[mt], &bh[sub * 2]);
                        mma16816(acc[mt][nt], al[mt], &bh[sub * 2]);
                        mma16816(acc[mt][nt], ah[mt], &bl[sub * 2]);
                    }
                }
            }
        }
        __syncthreads();
    }

    // Epilogue: scale by dinv[row], write fp32
    int g = lane >> 2;
    int cq = (lane & 3) * 2;
    #pragma unroll
    for (int mt = 0; mt < 2; mt++) {
        int row0 = r0 + wm + mt * 16 + g;
        int row1 = row0 + 8;
        float dv0 = (row0 < M) ? dinv[row0] : 0.f;
        float dv1 = (row1 < M) ? dinv[row1] : 0.f;
        #pragma unroll
        for (int nt = 0; nt < 8; nt++) {
            int col = n0c + wn + nt * 8 + cq;
            if (row0 < M) {
                float2 v = make_float2(acc[mt][nt][0] * dv0, acc[mt][nt][1] * dv0);
                *(float2*)(Hs + (size_t)row0 * C + col) = v;
            }
            if (row1 < M) {
                float2 v = make_float2(acc[mt][nt][2] * dv1, acc[mt][nt][3] * dv1);
                *(float2*)(Hs + (size_t)row1 * C + col) = v;
            }
        }
    }
}

// ---------------------------------------------------------------------------
// CSR gather: res = prelu((Hs[n] + sum_e Hs[src_e]) * dinv[n] + b)
// ---------------------------------------------------------------------------
template <int BF16OUT>
__global__ __launch_bounds__(256)
void gather_nodes(const float* __restrict__ Hs, float* __restrict__ outf,
                  __nv_bfloat16* __restrict__ ohi, __nv_bfloat16* __restrict__ olo,
                  const int* __restrict__ rowptr, const int* __restrict__ csrc,
                  const float* __restrict__ dinv, const float* __restrict__ bias,
                  const float* __restrict__ a_ptr, int n) {
    int node = blockIdx.x * (blockDim.x >> 5) + (threadIdx.x >> 5);
    if (node >= n) return;
    int lane = threadIdx.x & 31;

    const float4* self = (const float4*)(Hs + (size_t)node * C);
    float4 accA0 = __ldg(&self[lane]);
    float4 accA1 = __ldg(&self[lane + 32]);
    float4 accB0 = make_float4(0.f, 0.f, 0.f, 0.f);
    float4 accB1 = make_float4(0.f, 0.f, 0.f, 0.f);

    int beg = __ldg(&rowptr[node]);
    int end = __ldg(&rowptr[node + 1]);
    int p = beg;

    for (; p + 4 <= end; p += 4) {
        int s0 = __ldg(&csrc[p + 0]);
        int s1 = __ldg(&csrc[p + 1]);
        int s2 = __ldg(&csrc[p + 2]);
        int s3 = __ldg(&csrc[p + 3]);
        const float4* r0 = (const float4*)(Hs + (size_t)s0 * C);
        const float4* r1 = (const float4*)(Hs + (size_t)s1 * C);
        const float4* r2 = (const float4*)(Hs + (size_t)s2 * C);
        const float4* r3 = (const float4*)(Hs + (size_t)s3 * C);
        float4 v00 = __ldg(&r0[lane]);
        float4 v01 = __ldg(&r0[lane + 32]);
        float4 v10 = __ldg(&r1[lane]);
        float4 v11 = __ldg(&r1[lane + 32]);
        float4 v20 = __ldg(&r2[lane]);
        float4 v21 = __ldg(&r2[lane + 32]);
        float4 v30 = __ldg(&r3[lane]);
        float4 v31 = __ldg(&r3[lane + 32]);
        accA0.x += v00.x; accA0.y += v00.y; accA0.z += v00.z; accA0.w += v00.w;
        accA1.x += v01.x; accA1.y += v01.y; accA1.z += v01.z; accA1.w += v01.w;
        accB0.x += v10.x; accB0.y += v10.y; accB0.z += v10.z; accB0.w += v10.w;
        accB1.x += v11.x; accB1.y += v11.y; accB1.z += v11.z; accB1.w += v11.w;
        accA0.x += v20.x; accA0.y += v20.y; accA0.z += v20.z; accA0.w += v20.w;
        accA1.x += v21.x; accA1.y += v21.y; accA1.z += v21.z; accA1.w += v21.w;
        accB0.x += v30.x; accB0.y += v30.y; accB0.z += v30.z; accB0.w += v30.w;
        accB1.x += v31.x; accB1.y += v31.y; accB1.z += v31.z; accB1.w += v31.w;
    }
    for (; p < end; p++) {
        int s = __ldg(&csrc[p]);
        const float4* r = (const float4*)(Hs + (size_t)s * C);
        float4 v0 = __ldg(&r[lane]);
        float4 v1 = __ldg(&r[lane + 32]);
        accA0.x += v0.x; accA0.y += v0.y; accA0.z += v0.z; accA0.w += v0.w;
        accA1.x += v1.x; accA1.y += v1.y; accA1.z += v1.z; accA1.w += v1.w;
    }

    accA0.x += accB0.x; accA0.y += accB0.y; accA0.z += accB0.z; accA0.w += accB0.w;
    accA1.x += accB1.x; accA1.y += accB1.y; accA1.z += accB1.z; accA1.w += accB1.w;

    float dv = __ldg(&dinv[node]);
    float av = __ldg(a_ptr);
    float4 b0 = __ldg(&((const float4*)bias)[lane]);
    float4 b1 = __ldg(&((const float4*)bias)[lane + 32]);

    float o[8];
    o[0] = accA0.x * dv + b0.x;  o[1] = accA0.y * dv + b0.y;
    o[2] = accA0.z * dv + b0.z;  o[3] = accA0.w * dv + b0.w;
    o[4] = accA1.x * dv + b1.x;  o[5] = accA1.y * dv + b1.y;
    o[6] = accA1.z * dv + b1.z;  o[7] = accA1.w * dv + b1.w;
    #pragma unroll
    for (int j = 0; j < 8; j++) o[j] = o[j] >= 0.f ? o[j] : av * o[j];

    if (BF16OUT) {
        __nv_bfloat16 hs[8], ls[8];
        #pragma unroll
        for (int j = 0; j < 8; j++) split_bf16(o[j], hs[j], ls[j]);
        size_t base = (size_t)node * (C / 4);
        BF2 a, b; uint2 u;
        a.h2 = __nv_bfloat162(hs[0], hs[1]); b.h2 = __nv_bfloat162(hs[2], hs[3]);
        u.x = a.u; u.y = b.u; ((uint2*)ohi)[base + lane] = u;
        a.h2 = __nv_bfloat162(hs[4], hs[5]); b.h2 = __nv_bfloat162(hs[6], hs[7]);
        u.x = a.u; u.y = b.u; ((uint2*)ohi)[base + 32 + lane] = u;
        a.h2 = __nv_bfloat162(ls[0], ls[1]); b.h2 = __nv_bfloat162(ls[2], ls[3]);
        u.x = a.u; u.y = b.u; ((uint2*)olo)[base + lane] = u;
        a.h2 = __nv_bfloat162(ls[4], ls[5]); b.h2 = __nv_bfloat162(ls[6], ls[7]);
        u.x = a.u; u.y = b.u; ((uint2*)olo)[base + 32 + lane] = u;
    } else {
        float4* op = (float4*)(outf + (size_t)node * C);
        op[lane] = make_float4(o[0], o[1], o[2], o[3]);
        op[lane + 32] = make_float4(o[4], o[5], o[6], o[7]);
    }
}

// ---------------------------------------------------------------------------
// Launch: CSR chain on a forked side stream, overlapped with conv+GEMM1.
// ---------------------------------------------------------------------------
extern "C" void kernel_launch(void* const* d_in, const int* in_sizes, int n_in,
                              void* d_out, int out_size) {
    const float* x  = (const float*)d_in[0];
    const float* W1 = (const float*)d_in[1];
    const float* b1 = (const float*)d_in[2];
    const float* W2 = (const float*)d_in[3];
    const float* b2 = (const float*)d_in[4];
    const float* a  = (const float*)d_in[5];
    const int* eidx = (const int*)d_in[6];

    const int M = in_sizes[0] / C;     // 50000
    const int E = in_sizes[6] / 2;     // 800000
    const int* src = eidx;
    const int* dst = eidx + E;

    float *tbuf, *dinv;
    int *deg, *rowptr, *cursor, *csrc;
    __nv_bfloat16 *ahi, *alo, *w1hi, *w1lo, *w2hi, *w2lo;
    cudaGetSymbolAddress((void**)&tbuf, g_t);
    cudaGetSymbolAddress((void**)&dinv, g_dinv);
    cudaGetSymbolAddress((void**)&deg, g_deg);
    cudaGetSymbolAddress((void**)&rowptr, g_rowptr);
    cudaGetSymbolAddress((void**)&cursor, g_cursor);
    cudaGetSymbolAddress((void**)&csrc, g_csrc);
    cudaGetSymbolAddress((void**)&ahi, g_ahi);
    cudaGetSymbolAddress((void**)&alo, g_alo);
    cudaGetSymbolAddress((void**)&w1hi, g_w1hi);
    cudaGetSymbolAddress((void**)&w1lo, g_w1lo);
    cudaGetSymbolAddress((void**)&w2hi, g_w2hi);
    cudaGetSymbolAddress((void**)&w2lo, g_w2lo);
    float* outp = (float*)d_out;

    static cudaStream_t s_side = nullptr;
    static cudaEvent_t ev_fork = nullptr, ev_join = nullptr;
    if (!s_side) {
        cudaStreamCreateWithFlags(&s_side, cudaStreamNonBlocking);
        cudaEventCreateWithFlags(&ev_fork, cudaEventDisableTiming);
        cudaEventCreateWithFlags(&ev_join, cudaEventDisableTiming);
    }

    // --- fork: CSR build on side stream ---
    cudaEventRecord(ev_fork, 0);
    cudaStreamWaitEvent(s_side, ev_fork, 0);
    deg_init  <<<(M + 255) / 256, 256, 0, s_side>>>(deg, M);
    deg_accum <<<(E + 255) / 256, 256, 0, s_side>>>(dst, deg, E);
    scan_build<<<1, 1024, 0, s_side>>>(deg, rowptr, cursor, dinv, M);
    csr_fill  <<<(E + 255) / 256, 256, 0, s_side>>>(src, dst, cursor, csrc, E);
    cudaEventRecord(ev_join, s_side);

    // --- main stream: conversions + GEMM1 (no CSR dependency) ---
    // NOTE: mma_gemm's dinv scaling is in the epilogue; dinv is produced by
    // scan_build on the side stream, so GEMM1 must wait for it. Instead,
    // gemm epilogue reads dinv -> join must happen BEFORE gemm1.
    // To keep overlap, conv kernels run first (no dinv), then join, then gemm1.
    conv_x<<<(MPAD * (C / 4) + 255) / 256, 256>>>(x, ahi, alo, M);
    conv_w<<<(C * (C / 4) + 255) / 256, 256>>>(W1, w1hi, w1lo);
    conv_w<<<(C * (C / 4) + 255) / 256, 256>>>(W2, w2hi, w2lo);
    cudaStreamWaitEvent(0, ev_join, 0);

    dim3 ggrid((M + 127) / 128, 2);    // 391 x 2
    const int gblocks = (M + 7) / 8;

    // --- layer 1 ---
    mma_gemm<<<ggrid, 256>>>(ahi, alo, w1hi, w1lo, tbuf, dinv, M);
    gather_nodes<1><<<gblocks, 256>>>(tbuf, nullptr, ahi, alo, rowptr, csrc, dinv, b1, a, M);

    // --- layer 2 ---
    mma_gemm<<<ggrid, 256>>>(ahi, alo, w2hi, w2lo, tbuf, dinv, M);
    gather_nodes<0><<<gblocks, 256>>>(tbuf, outp, nullptr, nullptr, rowptr, csrc, dinv, b2, a, M);
}

// round 9
// speedup vs baseline: 1.2237x; 1.2237x over previous
#include <cuda_runtime.h>
#include <cuda_bf16.h>
#include <cstdint>

#define NN   50000
#define EE   800000
#define C    256
#define MPAD 50048          // 391 * 128

// ---------------------------------------------------------------------------
// Scratch (__device__ globals, allocation-free rule)
// ---------------------------------------------------------------------------
__device__ __align__(16) float g_t[(size_t)NN * C];            // GEMM out (raw H)
__device__ __align__(16) __nv_bfloat16 g_ahi[(size_t)MPAD * C];
__device__ __align__(16) __nv_bfloat16 g_alo[(size_t)MPAD * C];
__device__ __align__(16) __nv_bfloat16 g_w1hi[C * C];   // B^T layout [N][K]
__device__ __align__(16) __nv_bfloat16 g_w1lo[C * C];
__device__ __align__(16) __nv_bfloat16 g_w2hi[C * C];
__device__ __align__(16) __nv_bfloat16 g_w2lo[C * C];
__device__ float g_dinv[NN];
__device__ int   g_deg[NN];
__device__ int   g_rowptr[NN + 1];
__device__ int   g_cursor[NN];
__device__ int   g_csrc[EE];

__device__ __forceinline__ uint32_t smem_u32(const void* p) {
    uint32_t a;
    asm("{ .reg .u64 t; cvta.to.shared.u64 t, %1; cvt.u32.u64 %0, t; }"
        : "=r"(a) : "l"(p));
    return a;
}

// ---------------------------------------------------------------------------
// Degree / CSR build
// ---------------------------------------------------------------------------
__global__ void deg_init(int* deg, int n) {
    int i = blockIdx.x * blockDim.x + threadIdx.x;
    if (i < n) deg[i] = 0;
}
__global__ void deg_accum(const int* __restrict__ dst, int* deg, int e) {
    int i = blockIdx.x * blockDim.x + threadIdx.x;
    if (i < e) atomicAdd(&deg[dst[i]], 1);
}
__global__ void scan_build(const int* __restrict__ deg, int* __restrict__ row_ptr,
                           int* __restrict__ cursor, float* __restrict__ dinv, int n) {
    __shared__ int part[1024];
    const int T = 1024;
    int tid = threadIdx.x;
    int chunk = (n + T - 1) / T;
    int beg = tid * chunk;
    int end = min(beg + chunk, n);
    int s = 0;
    for (int i = beg; i < end; i++) s += deg[i];
    part[tid] = s;
    __syncthreads();
    for (int off = 1; off < T; off <<= 1) {
        int v = part[tid];
        int u = (tid >= off) ? part[tid - off] : 0;
        __syncthreads();
        part[tid] = v + u;
        __syncthreads();
    }
    int run = (tid > 0) ? part[tid - 1] : 0;
    for (int i = beg; i < end; i++) {
        int c = deg[i];
        row_ptr[i] = run;
        cursor[i] = run;
        dinv[i] = rsqrtf((float)(c + 1));
        run += c;
    }
    if (tid == T - 1) row_ptr[n] = part[T - 1];
}
__global__ void csr_fill(const int* __restrict__ src, const int* __restrict__ dst,
                         int* cursor, int* __restrict__ csrc, int e) {
    int i = blockIdx.x * blockDim.x + threadIdx.x;
    if (i < e) {
        int p = atomicAdd(&cursor[dst[i]], 1);
        csrc[p] = src[i];
    }
}

// ---------------------------------------------------------------------------
// Conversion: fp32 -> (bf16 hi, bf16 lo)
// ---------------------------------------------------------------------------
union BF2 { __nv_bfloat162 h2; uint32_t u; };

__device__ __forceinline__ void split_bf16(float v, __nv_bfloat16& hi, __nv_bfloat16& lo) {
    hi = __float2bfloat16(v);
    lo = __float2bfloat16(v - __bfloat162float(hi));
}

__global__ void conv_x(const float* __restrict__ x, __nv_bfloat16* __restrict__ hi,
                       __nv_bfloat16* __restrict__ lo, int M) {
    int i = blockIdx.x * blockDim.x + threadIdx.x;      // float4 index
    if (i >= MPAD * (C / 4)) return;
    int r = i >> 6;
    float4 v = (r < M) ? __ldg((const float4*)x + i) : make_float4(0.f, 0.f, 0.f, 0.f);
    __nv_bfloat16 h0, h1, h2, h3, l0, l1, l2, l3;
    split_bf16(v.x, h0, l0); split_bf16(v.y, h1, l1);
    split_bf16(v.z, h2, l2); split_bf16(v.w, h3, l3);
    BF2 a, b; uint2 o;
    a.h2 = __nv_bfloat162(h0, h1); b.h2 = __nv_bfloat162(h2, h3);
    o.x = a.u; o.y = b.u;
    ((uint2*)hi)[i] = o;
    a.h2 = __nv_bfloat162(l0, l1); b.h2 = __nv_bfloat162(l2, l3);
    o.x = a.u; o.y = b.u;
    ((uint2*)lo)[i] = o;
}

// W [K,N] fp32 -> B^T [N][K] bf16 hi/lo
__global__ void conv_w(const float* __restrict__ W, __nv_bfloat16* __restrict__ hi,
                       __nv_bfloat16* __restrict__ lo) {
    int i = blockIdx.x * blockDim.x + threadIdx.x;      // over 256*64
    if (i >= C * (C / 4)) return;
    int n = i >> 6;
    int k4 = (i & 63) * 4;
    __nv_bfloat16 hs[4], ls[4];
    #pragma unroll
    for (int j = 0; j < 4; j++)
        split_bf16(__ldg(&W[(size_t)(k4 + j) * C + n]), hs[j], ls[j]);
    BF2 a, b; uint2 o;
    a.h2 = __nv_bfloat162(hs[0], hs[1]); b.h2 = __nv_bfloat162(hs[2], hs[3]);
    o.x = a.u; o.y = b.u;
    ((uint2*)hi)[i] = o;
    a.h2 = __nv_bfloat162(ls[0], ls[1]); b.h2 = __nv_bfloat162(ls[2], ls[3]);
    o.x = a.u; o.y = b.u;
    ((uint2*)lo)[i] = o;
}

// ---------------------------------------------------------------------------
// mma.sync bf16 GEMM (R5-proven, dinv-free): H = Ahi*Bhi + Alo*Bhi + Ahi*Blo
// CTA 128x128, 8 warps of 32x64. K-chunks of 32. Bt is [N][K] ("col" operand).
// ---------------------------------------------------------------------------
#define LDS_PAD 40            // 32 + 8 pad (bf16 elems per smem row)

__device__ __forceinline__ void ldsm4(uint32_t* r, uint32_t addr) {
    asm volatile("ldmatrix.sync.aligned.m8n8.x4.shared.b16 {%0,%1,%2,%3}, [%4];"
                 : "=r"(r[0]), "=r"(r[1]), "=r"(r[2]), "=r"(r[3]) : "r"(addr));
}
__device__ __forceinline__ void mma16816(float* c, const uint32_t* a, const uint32_t* b) {
    asm volatile("mma.sync.aligned.m16n8k16.row.col.f32.bf16.bf16.f32 "
                 "{%0,%1,%2,%3}, {%4,%5,%6,%7}, {%8,%9}, {%0,%1,%2,%3};"
                 : "+f"(c[0]), "+f"(c[1]), "+f"(c[2]), "+f"(c[3])
                 : "r"(a[0]), "r"(a[1]), "r"(a[2]), "r"(a[3]), "r"(b[0]), "r"(b[1]));
}

__global__ __launch_bounds__(256)
void mma_gemm(const __nv_bfloat16* __restrict__ Ahi, const __nv_bfloat16* __restrict__ Alo,
              const __nv_bfloat16* __restrict__ Bhi, const __nv_bfloat16* __restrict__ Blo,
              float* __restrict__ Hs, int M) {
    __shared__ __nv_bfloat16 sAh[128][LDS_PAD];
    __shared__ __nv_bfloat16 sAl[128][LDS_PAD];
    __shared__ __nv_bfloat16 sBh[128][LDS_PAD];
    __shared__ __nv_bfloat16 sBl[128][LDS_PAD];

    int tid = threadIdx.x, lane = tid & 31, wid = tid >> 5;
    int r0 = blockIdx.x * 128;
    int n0c = blockIdx.y * 128;          // CTA col base
    int wm = (wid & 3) * 32;             // warp row offset in tile
    int wn = (wid >> 2) * 64;            // warp col offset in tile

    // ldmatrix lane address components
    int aRow = lane & 15;
    int aCol = (lane >> 4) * 8;
    int bRow = (lane & 7) + ((lane >> 4) == 1 ? 8 : 0);
    int bCol = ((lane >> 3) & 1) * 8;

    uint32_t sbAh = smem_u32(sAh), sbAl = smem_u32(sAl);
    uint32_t sbBh = smem_u32(sBh), sbBl = smem_u32(sBl);

    // global staging map: 512 uint4 per tile, 2 per thread
    int gi0 = tid, gi1 = tid + 256;
    int gr0 = gi0 >> 2, gc0 = (gi0 & 3) * 8;
    int gr1 = gi1 >> 2, gc1 = (gi1 & 3) * 8;

    float acc[2][8][4] = {};

    #pragma unroll 1
    for (int kc = 0; kc < 8; kc++) {
        int k0 = kc * 32;
        {
            const char* pAh = (const char*)(Ahi + (size_t)(r0 + gr0) * C + k0 + gc0);
            const char* pAl = (const char*)(Alo + (size_t)(r0 + gr0) * C + k0 + gc0);
            const char* pBh = (const char*)(Bhi + (size_t)(n0c + gr0) * C + k0 + gc0);
            const char* pBl = (const char*)(Blo + (size_t)(n0c + gr0) * C + k0 + gc0);
            *(uint4*)&sAh[gr0][gc0] = *(const uint4*)pAh;
            *(uint4*)&sAl[gr0][gc0] = *(const uint4*)pAl;
            *(uint4*)&sBh[gr0][gc0] = *(const uint4*)pBh;
            *(uint4*)&sBl[gr0][gc0] = *(const uint4*)pBl;
            const char* qAh = (const char*)(Ahi + (size_t)(r0 + gr1) * C + k0 + gc1);
            const char* qAl = (const char*)(Alo + (size_t)(r0 + gr1) * C + k0 + gc1);
            const char* qBh = (const char*)(Bhi + (size_t)(n0c + gr1) * C + k0 + gc1);
            const char* qBl = (const char*)(Blo + (size_t)(n0c + gr1) * C + k0 + gc1);
            *(uint4*)&sAh[gr1][gc1] = *(const uint4*)qAh;
            *(uint4*)&sAl[gr1][gc1] = *(const uint4*)qAl;
            *(uint4*)&sBh[gr1][gc1] = *(const uint4*)qBh;
            *(uint4*)&sBl[gr1][gc1] = *(const uint4*)qBl;
        }
        __syncthreads();

        #pragma unroll
        for (int ks = 0; ks < 32; ks += 16) {
            uint32_t ah[2][4], al[2][4];
            #pragma unroll
            for (int mt = 0; mt < 2; mt++) {
                uint32_t off = (uint32_t)((wm + mt * 16 + aRow) * LDS_PAD + ks + aCol) * 2;
                ldsm4(ah[mt], sbAh + off);
                ldsm4(al[mt], sbAl + off);
            }
            #pragma unroll
            for (int nq = 0; nq < 4; nq++) {
                uint32_t bh[4], bl[4];
                uint32_t off = (uint32_t)((wn + nq * 16 + bRow) * LDS_PAD + ks + bCol) * 2;
                ldsm4(bh, sbBh + off);
                ldsm4(bl, sbBl + off);
                #pragma unroll
                for (int sub = 0; sub < 2; sub++) {
                    int nt = nq * 2 + sub;
                    #pragma unroll
                    for (int mt = 0; mt < 2; mt++) {
                        mma16816(acc[mt][nt], ah[mt], &bh[sub * 2]);
                        mma16816(acc[mt][nt], al[mt], &bh[sub * 2]);
                        mma16816(acc[mt][nt], ah[mt], &bl[sub * 2]);
                    }
                }
            }
        }
        __syncthreads();
    }

    // Epilogue: write raw H (no dinv — keeps GEMM independent of CSR chain)
    int g = lane >> 2;
    int cq = (lane & 3) * 2;
    #pragma unroll
    for (int mt = 0; mt < 2; mt++) {
        int row0 = r0 + wm + mt * 16 + g;
        int row1 = row0 + 8;
        #pragma unroll
        for (int nt = 0; nt < 8; nt++) {
            int col = n0c + wn + nt * 8 + cq;
            if (row0 < M) {
                float2 v = make_float2(acc[mt][nt][0], acc[mt][nt][1]);
                *(float2*)(Hs + (size_t)row0 * C + col) = v;
            }
            if (row1 < M) {
                float2 v = make_float2(acc[mt][nt][2], acc[mt][nt][3]);
                *(float2*)(Hs + (size_t)row1 * C + col) = v;
            }
        }
    }
}

// ---------------------------------------------------------------------------
// CSR gather (normalization absorbed here):
// out[d] = prelu(dinv[d]*(sum_e dinv[s_e]*H[s_e] + dinv[d]*H[d]) + b)
// ---------------------------------------------------------------------------
template <int BF16OUT>
__global__ __launch_bounds__(256)
void gather_nodes(const float* __restrict__ Hs, float* __restrict__ outf,
                  __nv_bfloat16* __restrict__ ohi, __nv_bfloat16* __restrict__ olo,
                  const int* __restrict__ rowptr, const int* __restrict__ csrc,
                  const float* __restrict__ dinv, const float* __restrict__ bias,
                  const float* __restrict__ a_ptr, int n) {
    int node = blockIdx.x * (blockDim.x >> 5) + (threadIdx.x >> 5);
    if (node >= n) return;
    int lane = threadIdx.x & 31;

    float dvn = __ldg(&dinv[node]);
    const float4* self = (const float4*)(Hs + (size_t)node * C);
    float4 s0v = __ldg(&self[lane]);
    float4 s1v = __ldg(&self[lane + 32]);
    float4 accA0 = make_float4(s0v.x * dvn, s0v.y * dvn, s0v.z * dvn, s0v.w * dvn);
    float4 accA1 = make_float4(s1v.x * dvn, s1v.y * dvn, s1v.z * dvn, s1v.w * dvn);
    float4 accB0 = make_float4(0.f, 0.f, 0.f, 0.f);
    float4 accB1 = make_float4(0.f, 0.f, 0.f, 0.f);

    int beg = __ldg(&rowptr[node]);
    int end = __ldg(&rowptr[node + 1]);
    int p = beg;

    for (; p + 4 <= end; p += 4) {
        int s0 = __ldg(&csrc[p + 0]);
        int s1 = __ldg(&csrc[p + 1]);
        int s2 = __ldg(&csrc[p + 2]);
        int s3 = __ldg(&csrc[p + 3]);
        float d0 = __ldg(&dinv[s0]);
        float d1 = __ldg(&dinv[s1]);
        float d2 = __ldg(&dinv[s2]);
        float d3 = __ldg(&dinv[s3]);
        const float4* r0 = (const float4*)(Hs + (size_t)s0 * C);
        const float4* r1 = (const float4*)(Hs + (size_t)s1 * C);
        const float4* r2 = (const float4*)(Hs + (size_t)s2 * C);
        const float4* r3 = (const float4*)(Hs + (size_t)s3 * C);
        float4 v00 = __ldg(&r0[lane]);
        float4 v01 = __ldg(&r0[lane + 32]);
        float4 v10 = __ldg(&r1[lane]);
        float4 v11 = __ldg(&r1[lane + 32]);
        float4 v20 = __ldg(&r2[lane]);
        float4 v21 = __ldg(&r2[lane + 32]);
        float4 v30 = __ldg(&r3[lane]);
        float4 v31 = __ldg(&r3[lane + 32]);
        accA0.x += v00.x * d0; accA0.y += v00.y * d0; accA0.z += v00.z * d0; accA0.w += v00.w * d0;
        accA1.x += v01.x * d0; accA1.y += v01.y * d0; accA1.z += v01.z * d0; accA1.w += v01.w * d0;
        accB0.x += v10.x * d1; accB0.y += v10.y * d1; accB0.z += v10.z * d1; accB0.w += v10.w * d1;
        accB1.x += v11.x * d1; accB1.y += v11.y * d1; accB1.z += v11.z * d1; accB1.w += v11.w * d1;
        accA0.x += v20.x * d2; accA0.y += v20.y * d2; accA0.z += v20.z * d2; accA0.w += v20.w * d2;
        accA1.x += v21.x * d2; accA1.y += v21.y * d2; accA1.z += v21.z * d2; accA1.w += v21.w * d2;
        accB0.x += v30.x * d3; accB0.y += v30.y * d3; accB0.z += v30.z * d3; accB0.w += v30.w * d3;
        accB1.x += v31.x * d3; accB1.y += v31.y * d3; accB1.z += v31.z * d3; accB1.w += v31.w * d3;
    }
    for (; p < end; p++) {
        int s = __ldg(&csrc[p]);
        float ds = __ldg(&dinv[s]);
        const float4* r = (const float4*)(Hs + (size_t)s * C);
        float4 v0 = __ldg(&r[lane]);
        float4 v1 = __ldg(&r[lane + 32]);
        accA0.x += v0.x * ds; accA0.y += v0.y * ds; accA0.z += v0.z * ds; accA0.w += v0.w * ds;
        accA1.x += v1.x * ds; accA1.y += v1.y * ds; accA1.z += v1.z * ds; accA1.w += v1.w * ds;
    }

    accA0.x += accB0.x; accA0.y += accB0.y; accA0.z += accB0.z; accA0.w += accB0.w;
    accA1.x += accB1.x; accA1.y += accB1.y; accA1.z += accB1.z; accA1.w += accB1.w;

    float av = __ldg(a_ptr);
    float4 b0 = __ldg(&((const float4*)bias)[lane]);
    float4 b1 = __ldg(&((const float4*)bias)[lane + 32]);

    float o[8];
    o[0] = accA0.x * dvn + b0.x;  o[1] = accA0.y * dvn + b0.y;
    o[2] = accA0.z * dvn + b0.z;  o[3] = accA0.w * dvn + b0.w;
    o[4] = accA1.x * dvn + b1.x;  o[5] = accA1.y * dvn + b1.y;
    o[6] = accA1.z * dvn + b1.z;  o[7] = accA1.w * dvn + b1.w;
    #pragma unroll
    for (int j = 0; j < 8; j++) o[j] = o[j] >= 0.f ? o[j] : av * o[j];

    if (BF16OUT) {
        __nv_bfloat16 hs[8], ls[8];
        #pragma unroll
        for (int j = 0; j < 8; j++) split_bf16(o[j], hs[j], ls[j]);
        size_t base = (size_t)node * (C / 4);
        BF2 a, b; uint2 u;
        a.h2 = __nv_bfloat162(hs[0], hs[1]); b.h2 = __nv_bfloat162(hs[2], hs[3]);
        u.x = a.u; u.y = b.u; ((uint2*)ohi)[base + lane] = u;
        a.h2 = __nv_bfloat162(hs[4], hs[5]); b.h2 = __nv_bfloat162(hs[6], hs[7]);
        u.x = a.u; u.y = b.u; ((uint2*)ohi)[base + 32 + lane] = u;
        a.h2 = __nv_bfloat162(ls[0], ls[1]); b.h2 = __nv_bfloat162(ls[2], ls[3]);
        u.x = a.u; u.y = b.u; ((uint2*)olo)[base + lane] = u;
        a.h2 = __nv_bfloat162(ls[4], ls[5]); b.h2 = __nv_bfloat162(ls[6], ls[7]);
        u.x = a.u; u.y = b.u; ((uint2*)olo)[base + 32 + lane] = u;
    } else {
        float4* op = (float4*)(outf + (size_t)node * C);
        op[lane] = make_float4(o[0], o[1], o[2], o[3]);
        op[lane + 32] = make_float4(o[4], o[5], o[6], o[7]);
    }
}

// ---------------------------------------------------------------------------
// Launch: CSR chain on side stream fully hidden under conv + GEMM1.
// ---------------------------------------------------------------------------
extern "C" void kernel_launch(void* const* d_in, const int* in_sizes, int n_in,
                              void* d_out, int out_size) {
    const float* x  = (const float*)d_in[0];
    const float* W1 = (const float*)d_in[1];
    const float* b1 = (const float*)d_in[2];
    const float* W2 = (const float*)d_in[3];
    const float* b2 = (const float*)d_in[4];
    const float* a  = (const float*)d_in[5];
    const int* eidx = (const int*)d_in[6];

    const int M = in_sizes[0] / C;     // 50000
    const int E = in_sizes[6] / 2;     // 800000
    const int* src = eidx;
    const int* dst = eidx + E;

    float *tbuf, *dinv;
    int *deg, *rowptr, *cursor, *csrc;
    __nv_bfloat16 *ahi, *alo, *w1hi, *w1lo, *w2hi, *w2lo;
    cudaGetSymbolAddress((void**)&tbuf, g_t);
    cudaGetSymbolAddress((void**)&dinv, g_dinv);
    cudaGetSymbolAddress((void**)&deg, g_deg);
    cudaGetSymbolAddress((void**)&rowptr, g_rowptr);
    cudaGetSymbolAddress((void**)&cursor, g_cursor);
    cudaGetSymbolAddress((void**)&csrc, g_csrc);
    cudaGetSymbolAddress((void**)&ahi, g_ahi);
    cudaGetSymbolAddress((void**)&alo, g_alo);
    cudaGetSymbolAddress((void**)&w1hi, g_w1hi);
    cudaGetSymbolAddress((void**)&w1lo, g_w1lo);
    cudaGetSymbolAddress((void**)&w2hi, g_w2hi);
    cudaGetSymbolAddress((void**)&w2lo, g_w2lo);
    float* outp = (float*)d_out;

    static cudaStream_t s_side = nullptr;
    static cudaEvent_t ev_fork = nullptr, ev_join = nullptr;
    if (!s_side) {
        cudaStreamCreateWithFlags(&s_side, cudaStreamNonBlocking);
        cudaEventCreateWithFlags(&ev_fork, cudaEventDisableTiming);
        cudaEventCreateWithFlags(&ev_join, cudaEventDisableTiming);
    }

    // --- fork: CSR build + dinv on side stream ---
    cudaEventRecord(ev_fork, 0);
    cudaStreamWaitEvent(s_side, ev_fork, 0);
    deg_init  <<<(M + 255) / 256, 256, 0, s_side>>>(deg, M);
    deg_accum <<<(E + 255) / 256, 256, 0, s_side>>>(dst, deg, E);
    scan_build<<<1, 1024, 0, s_side>>>(deg, rowptr, cursor, dinv, M);
    csr_fill  <<<(E + 255) / 256, 256, 0, s_side>>>(src, dst, cursor, csrc, E);
    cudaEventRecord(ev_join, s_side);

    // --- main stream: conv + GEMM1 (all dinv-free; CSR chain hides underneath)
    conv_x<<<(MPAD * (C / 4) + 255) / 256, 256>>>(x, ahi, alo, M);
    conv_w<<<(C * (C / 4) + 255) / 256, 256>>>(W1, w1hi, w1lo);
    conv_w<<<(C * (C / 4) + 255) / 256, 256>>>(W2, w2hi, w2lo);

    dim3 ggrid((M + 127) / 128, 2);    // 391 x 2
    const int gblocks = (M + 7) / 8;

    mma_gemm<<<ggrid, 256>>>(ahi, alo, w1hi, w1lo, tbuf, M);

    // join: gathers need dinv + CSR
    cudaStreamWaitEvent(0, ev_join, 0);
    gather_nodes<1><<<gblocks, 256>>>(tbuf, nullptr, ahi, alo, rowptr, csrc, dinv, b1, a, M);

    // --- layer 2 ---
    mma_gemm<<<ggrid, 256>>>(ahi, alo, w2hi, w2lo, tbuf, M);
    gather_nodes<0><<<gblocks, 256>>>(tbuf, outp, nullptr, nullptr, rowptr, csrc, dinv, b2, a, M);
}